// round 10
// baseline (speedup 1.0000x reference)
#include <cuda_runtime.h>
#include <cstdint>
#include <cstddef>

#define NNODES 50000
#define NEDGES 800000
#define NTYPES 3
#define DIM    64
#define EPSLN  1e-5f

typedef unsigned long long ull;

// ---------------- device scratch -------------------------------------------
__device__ __align__(16) float g_A[(size_t)NTYPES * NNODES * DIM];
__device__ __align__(16) float g_B[(size_t)NTYPES * NNODES * DIM];
__device__ __align__(16) float g_acc[(size_t)NTYPES * NNODES * DIM];
__device__ __align__(8)  int2  g_idx[(size_t)NTYPES * NEDGES];   // {src,dst}
__device__ int   g_deg[NTYPES * NNODES];
__device__ float g_sum[NTYPES * DIM];
__device__ float g_sq[NTYPES * DIM];
__device__ float g_s[NTYPES * DIM];
__device__ float g_c[NTYPES * DIM];
__device__ int   g_is64;

// fast ELU: |err| <= ~5e-7 absolute (validated rel_err ~1e-6)
__device__ __forceinline__ float elu(float x) {
    return x > 0.f ? x : (__expf(x) - 1.f);
}

// ---------------- edge-index dtype detection --------------------------------
__global__ void k_detect(const int* __restrict__ e) {
    if (threadIdx.x == 0 && blockIdx.x == 0) {
        int is64 = 1;
        for (int i = 1; i < 256; i += 2)
            if (e[i] != 0) { is64 = 0; break; }
        g_is64 = is64;
    }
}

// ---------------- index conversion: (src,dst) -> packed int2 -----------------
__global__ void __launch_bounds__(256) k_convert(const void* __restrict__ esrc_raw,
                                                 const void* __restrict__ edst_raw) {
    const size_t i = (size_t)blockIdx.x * 256 + threadIdx.x;
    if (i >= (size_t)NTYPES * NEDGES) return;
    int s, d;
    if (g_is64) {
        s = (int)((const long long*)esrc_raw)[i];
        d = (int)((const long long*)edst_raw)[i];
    } else {
        s = ((const int*)esrc_raw)[i];
        d = ((const int*)edst_raw)[i];
    }
    g_idx[i] = make_int2(s, d);
}

// ---------------- zero-init --------------------------------------------------
__global__ void k_zero() {
    size_t stride = (size_t)gridDim.x * blockDim.x;
    size_t i = (size_t)blockIdx.x * blockDim.x + threadIdx.x;
    float4 z = make_float4(0.f, 0.f, 0.f, 0.f);
    float4* a4 = reinterpret_cast<float4*>(g_acc);
    size_t n4 = (size_t)NTYPES * NNODES * DIM / 4;
    for (size_t k = i; k < n4; k += stride) a4[k] = z;
    for (size_t k = i; k < (size_t)NTYPES * NNODES; k += stride) g_deg[k] = 0;
    if (i < NTYPES * DIM) { g_sum[i] = 0.f; g_sq[i] = 0.f; }
}

// ---------------- per-node precompute (vectorized) ---------------------------
__global__ void __launch_bounds__(256) k_pre(const float* __restrict__ F,
                                             const float* __restrict__ W1,
                                             const float* __restrict__ b1) {
    __shared__ float Fs[64 * 68];   // pad 68: 16B-aligned float4 rows
    __shared__ float Ws[64 * 64];
    const int tid = threadIdx.x;
    const int t = blockIdx.y;
    const int half = blockIdx.z;

    const float* Wsrc = W1 + ((size_t)t * 128 + (size_t)half * 64) * 64;
    for (int i = tid; i < 1024; i += 256)
        reinterpret_cast<float4*>(Ws)[i] = reinterpret_cast<const float4*>(Wsrc)[i];

    const int nl = tid >> 2, q = tid & 3;
    const int n = blockIdx.x * 64 + nl;
    {
        const int nc = (n < NNODES) ? n : (NNODES - 1);
        const float4* fr = reinterpret_cast<const float4*>(F + (size_t)nc * DIM + q * 16);
        const float mask = (n < NNODES) ? 1.f : 0.f;
#pragma unroll
        for (int i = 0; i < 4; i++) {
            float4 v = fr[i];
            v.x *= mask; v.y *= mask; v.z *= mask; v.w *= mask;
            *reinterpret_cast<float4*>(&Fs[nl * 68 + q * 16 + i * 4]) = v;
        }
    }
    __syncthreads();

    const int ng = (tid >> 4) << 2;
    const int og = (tid & 15) << 2;
    float acc[4][4] = {};
#pragma unroll 16
    for (int k = 0; k < 64; k++) {
        float a[4];
#pragma unroll
        for (int i = 0; i < 4; i++) a[i] = Fs[(ng + i) * 68 + k];
        float4 w = *reinterpret_cast<const float4*>(&Ws[k * 64 + og]);
        const float wa[4] = {w.x, w.y, w.z, w.w};
#pragma unroll
        for (int i = 0; i < 4; i++)
#pragma unroll
            for (int j = 0; j < 4; j++) acc[i][j] += a[i] * wa[j];
    }

    float bb[4] = {0.f, 0.f, 0.f, 0.f};
    if (half == 0) {
        float4 bv = *reinterpret_cast<const float4*>(&b1[t * DIM + og]);
        bb[0] = bv.x; bb[1] = bv.y; bb[2] = bv.z; bb[3] = bv.w;
    }
    float* dst = (half ? g_B : g_A);
#pragma unroll
    for (int i = 0; i < 4; i++) {
        int nn = blockIdx.x * 64 + ng + i;
        if (nn < NNODES) {
            float4 r = make_float4(acc[i][0] + bb[0], acc[i][1] + bb[1],
                                   acc[i][2] + bb[2], acc[i][3] + bb[3]);
            *reinterpret_cast<float4*>(
                &dst[(((size_t)t * NNODES + nn) << 6) + og]) = r;
        }
    }
}

// ---------------- main edge kernel (R2 tiling + out-packed FFMA2 phase B) ----
// 64 edges per CTA, 256 threads. Dynamic smem:
//   hnT_d  ull[64][66]  ({h,h} dup pairs, [ch][edge], pad 66)  0      33792
//   W2s    float[64][64]                                       33792  16384
//   sSum/sSq float[64]                                         50176 / 50432
//   dsts   int[64]                                             50688
//   s_lng/s_lnb/s_b2 float[64]                                 50944 / 51200 / 51456
extern __shared__ char smem_raw[];
#define SM_HNTD  ((ull*)smem_raw)
#define SM_W2S   ((float*)(smem_raw + 33792))
#define SM_SSUM  ((float*)(smem_raw + 50176))
#define SM_SSQ   ((float*)(smem_raw + 50432))
#define SM_DSTS  ((int*)(smem_raw + 50688))
#define SM_LNG   ((float*)(smem_raw + 50944))
#define SM_LNB   ((float*)(smem_raw + 51200))
#define SM_B2    ((float*)(smem_raw + 51456))
#define SMEM_BYTES 51712

__global__ void __launch_bounds__(256) k_edge(const float* __restrict__ lng,
                                              const float* __restrict__ lnb,
                                              const float* __restrict__ W2,
                                              const float* __restrict__ b2) {
    const int tid = threadIdx.x;
    const int t = blockIdx.y;

    const float* W2p = W2 + (size_t)t * 64 * 64;
    for (int i = tid; i < 1024; i += 256)
        reinterpret_cast<float4*>(SM_W2S)[i] = reinterpret_cast<const float4*>(W2p)[i];
    if (tid < 64) {
        SM_LNG[tid] = lng[t * DIM + tid];
        SM_LNB[tid] = lnb[t * DIM + tid];
        SM_B2[tid]  = b2[t * DIM + tid];
        SM_SSUM[tid] = 0.f; SM_SSQ[tid] = 0.f;
    }
    __syncthreads();

    // ---------- phase A: gather + ELU + LayerNorm -> duplicated hnT ----------
    const int el = tid >> 2, q = tid & 3;
    const size_t ge = (size_t)blockIdx.x * 64 + el;     // 12500*64 == NEDGES
    const int2 sd = g_idx[(size_t)t * NEDGES + ge];
    const int src = sd.x, dst = sd.y;

    float h[16];
    float sm = 0.f, sq = 0.f;
    {
        const float4* ap = reinterpret_cast<const float4*>(
            g_A + (((size_t)t * NNODES + (size_t)src) << 6) + q * 16);
        const float4* bp = reinterpret_cast<const float4*>(
            g_B + (((size_t)t * NNODES + (size_t)dst) << 6) + q * 16);
        float4 av[4], bv[4];
#pragma unroll
        for (int i = 0; i < 4; i++) av[i] = ap[i];
#pragma unroll
        for (int i = 0; i < 4; i++) bv[i] = bp[i];
#pragma unroll
        for (int i = 0; i < 4; i++) {
            float v0 = elu(av[i].x + bv[i].x), v1 = elu(av[i].y + bv[i].y);
            float v2 = elu(av[i].z + bv[i].z), v3 = elu(av[i].w + bv[i].w);
            h[i * 4 + 0] = v0; h[i * 4 + 1] = v1;
            h[i * 4 + 2] = v2; h[i * 4 + 3] = v3;
            sm += v0 + v1 + v2 + v3;
            sq += v0 * v0 + v1 * v1 + v2 * v2 + v3 * v3;
        }
    }
    sm += __shfl_xor_sync(0xffffffffu, sm, 1);
    sq += __shfl_xor_sync(0xffffffffu, sq, 1);
    sm += __shfl_xor_sync(0xffffffffu, sm, 2);
    sq += __shfl_xor_sync(0xffffffffu, sq, 2);
    const float mu = sm * (1.f / 64.f);
    const float var = sq * (1.f / 64.f) - mu * mu;
    const float rstd = rsqrtf(var + EPSLN);
#pragma unroll
    for (int i = 0; i < 16; i++) {
        const int ch = q * 16 + i;
        const float hn = (h[i] - mu) * rstd * SM_LNG[ch] + SM_LNB[ch];
        const unsigned int u = __float_as_uint(hn);
        SM_HNTD[ch * 66 + el] = (ull)u | ((ull)u << 32);   // {h,h}
    }
    if (q == 0) SM_DSTS[el] = dst;
    __syncthreads();

    // ---------- phase B: P = hn @ W2, out-packed FFMA2, 4e x 4o / thread -----
    const int eg = (tid >> 4) << 2;    // broadcast operand within warp
    const int og = (tid & 15) << 2;    // 16-way spread operand
    ull acc[4][2];
#pragma unroll
    for (int i = 0; i < 4; i++) { acc[i][0] = 0ull; acc[i][1] = 0ull; }

    const ull* hp = SM_HNTD + eg;
    const float* wp = SM_W2S + og;
#pragma unroll 16
    for (int m = 0; m < 64; m++) {
        ulonglong2 h01 = *reinterpret_cast<const ulonglong2*>(hp);
        ulonglong2 h23 = *reinterpret_cast<const ulonglong2*>(hp + 2);
        hp += 66;
        ulonglong2 wv = *reinterpret_cast<const ulonglong2*>(wp);   // outs og..og+3
        wp += 64;
        const ull hv[4] = {h01.x, h01.y, h23.x, h23.y};
#pragma unroll
        for (int i = 0; i < 4; i++) {
            asm("fma.rn.f32x2 %0, %1, %2, %0;" : "+l"(acc[i][0]) : "l"(hv[i]), "l"(wv.x));
            asm("fma.rn.f32x2 %0, %1, %2, %0;" : "+l"(acc[i][1]) : "l"(hv[i]), "l"(wv.y));
        }
    }

    // ---------- phase C: bias + ELU + scatter + BN stats ---------------------
    float4 bv = *reinterpret_cast<const float4*>(&SM_B2[og]);
    const float ba[4] = {bv.x, bv.y, bv.z, bv.w};
    float cs[4] = {0.f, 0.f, 0.f, 0.f}, cq[4] = {0.f, 0.f, 0.f, 0.f};
#pragma unroll
    for (int i = 0; i < 4; i++) {
        const int d = SM_DSTS[eg + i];
        const float2 p01 = *reinterpret_cast<const float2*>(&acc[i][0]);
        const float2 p23 = *reinterpret_cast<const float2*>(&acc[i][1]);
        const float p0 = elu(p01.x + ba[0]);
        const float p1 = elu(p01.y + ba[1]);
        const float p2 = elu(p23.x + ba[2]);
        const float p3 = elu(p23.y + ba[3]);
        float* addr = g_acc + (((size_t)t * NNODES + d) << 6) + og;
        asm volatile("red.global.add.v4.f32 [%0], {%1,%2,%3,%4};"
                     :: "l"(addr), "f"(p0), "f"(p1), "f"(p2), "f"(p3)
                     : "memory");
        cs[0] += p0; cs[1] += p1; cs[2] += p2; cs[3] += p3;
        cq[0] += p0 * p0; cq[1] += p1 * p1;
        cq[2] += p2 * p2; cq[3] += p3 * p3;
    }
    if ((tid & 15) == 0) {
#pragma unroll
        for (int i = 0; i < 4; i++)
            atomicAdd(&g_deg[t * NNODES + SM_DSTS[eg + i]], 1);
    }
#pragma unroll
    for (int j = 0; j < 4; j++) {
        cs[j] += __shfl_xor_sync(0xffffffffu, cs[j], 16);
        cq[j] += __shfl_xor_sync(0xffffffffu, cq[j], 16);
    }
    if ((tid & 31) < 16) {
#pragma unroll
        for (int j = 0; j < 4; j++) {
            atomicAdd(&SM_SSUM[og + j], cs[j]);
            atomicAdd(&SM_SSQ[og + j], cq[j]);
        }
    }
    __syncthreads();
    if (tid < 64) {
        atomicAdd(&g_sum[t * DIM + tid], SM_SSUM[tid]);
        atomicAdd(&g_sq[t * DIM + tid], SM_SSQ[tid]);
    }
}

// ---------------- BN stats finalize ------------------------------------------
__global__ void k_stats(const float* __restrict__ bng, const float* __restrict__ bnb) {
    int i = threadIdx.x;
    if (i < NTYPES * DIM) {
        float mean = g_sum[i] * (1.f / NEDGES);
        float var = g_sq[i] * (1.f / NEDGES) - mean * mean;
        float s = bng[i] * rsqrtf(fmaxf(var, 0.f) + EPSLN);
        g_s[i] = s;
        g_c[i] = bnb[i] - mean * s;
    }
}

// ---------------- final ------------------------------------------------------
__global__ void __launch_bounds__(256) k_final(const float* __restrict__ F,
                                               const float* __restrict__ Wr,
                                               const float* __restrict__ br,
                                               float* __restrict__ out) {
    __shared__ float Ws[64 * 64];
    __shared__ float aT[64 * 72];
    const int tid = threadIdx.x;
    for (int i = tid; i < 1024; i += 256)
        reinterpret_cast<float4*>(Ws)[i] = reinterpret_cast<const float4*>(Wr)[i];

    const int nl = tid >> 2, q = tid & 3;
    const int n = blockIdx.x * 64 + nl;
    float v[16];
#pragma unroll
    for (int i = 0; i < 16; i++) v[i] = 0.f;
    if (n < NNODES) {
#pragma unroll
        for (int t = 0; t < NTYPES; t++) {
            const float4* op = reinterpret_cast<const float4*>(
                g_acc + (((size_t)t * NNODES + n) << 6) + q * 16);
            float dg = (float)g_deg[t * NNODES + n];
#pragma unroll
            for (int i = 0; i < 4; i++) {
                float4 o = op[i];
                int ch = q * 16 + i * 4;
                v[i * 4 + 0] += o.x * g_s[t * DIM + ch + 0] + dg * g_c[t * DIM + ch + 0];
                v[i * 4 + 1] += o.y * g_s[t * DIM + ch + 1] + dg * g_c[t * DIM + ch + 1];
                v[i * 4 + 2] += o.z * g_s[t * DIM + ch + 2] + dg * g_c[t * DIM + ch + 2];
                v[i * 4 + 3] += o.w * g_s[t * DIM + ch + 3] + dg * g_c[t * DIM + ch + 3];
            }
        }
    }
#pragma unroll
    for (int i = 0; i < 16; i++) aT[(q * 16 + i) * 72 + nl] = v[i];
    __syncthreads();

    const int ng = (tid >> 4) << 2;
    const int og = (tid & 15) << 2;
    float acc[4][4] = {};
    const float* apx = &aT[ng];
    const float* wpx = &Ws[og];
#pragma unroll 16
    for (int k = 0; k < 64; k++) {
        float4 av = *reinterpret_cast<const float4*>(apx); apx += 72;
        float4 wv = *reinterpret_cast<const float4*>(wpx); wpx += 64;
        const float aa[4] = {av.x, av.y, av.z, av.w};
        const float wa[4] = {wv.x, wv.y, wv.z, wv.w};
#pragma unroll
        for (int i = 0; i < 4; i++)
#pragma unroll
            for (int j = 0; j < 4; j++) acc[i][j] += aa[i] * wa[j];
    }

    float4 brv = *reinterpret_cast<const float4*>(&br[og]);
    const float bra[4] = {brv.x, brv.y, brv.z, brv.w};
#pragma unroll
    for (int i = 0; i < 4; i++) {
        int nn = blockIdx.x * 64 + ng + i;
        if (nn < NNODES) {
            float4 f = *reinterpret_cast<const float4*>(&F[(size_t)nn * DIM + og]);
            float4 r = make_float4(acc[i][0] + bra[0] + f.x,
                                   acc[i][1] + bra[1] + f.y,
                                   acc[i][2] + bra[2] + f.z,
                                   acc[i][3] + bra[3] + f.w);
            *reinterpret_cast<float4*>(&out[(size_t)nn * DIM + og]) = r;
        }
    }
}

// ---------------- launch ------------------------------------------------------
extern "C" void kernel_launch(void* const* d_in, const int* in_sizes, int n_in,
                              void* d_out, int out_size) {
    const float* F   = (const float*)d_in[0];
    const float* W1  = (const float*)d_in[1];
    const float* b1  = (const float*)d_in[2];
    const float* lng = (const float*)d_in[3];
    const float* lnb = (const float*)d_in[4];
    const float* W2  = (const float*)d_in[5];
    const float* b2  = (const float*)d_in[6];
    const float* bng = (const float*)d_in[7];
    const float* bnb = (const float*)d_in[8];
    const float* Wr  = (const float*)d_in[9];
    const float* br  = (const float*)d_in[10];
    const void*  esrc = d_in[11];
    const void*  edst = d_in[12];

    cudaFuncSetAttribute(k_edge, cudaFuncAttributeMaxDynamicSharedMemorySize,
                         SMEM_BYTES);

    k_detect<<<1, 32>>>((const int*)esrc);
    k_convert<<<(NTYPES * NEDGES + 255) / 256, 256>>>(esrc, edst);
    k_zero<<<2048, 256>>>();

    dim3 gpre((NNODES + 63) / 64, NTYPES, 2);
    k_pre<<<gpre, 256>>>(F, W1, b1);

    dim3 gedge(NEDGES / 64, NTYPES, 1);
    k_edge<<<gedge, 256, SMEM_BYTES>>>(lng, lnb, W2, b2);

    k_stats<<<1, 256>>>(bng, bnb);

    k_final<<<(NNODES + 63) / 64, 256>>>(F, Wr, br, (float*)d_out);
}

// round 12
// speedup vs baseline: 1.4919x; 1.4919x over previous
#include <cuda_runtime.h>
#include <cstdint>
#include <cstddef>

#define NNODES 50000
#define NEDGES 800000
#define NTYPES 3
#define DIM    64
#define EPSLN  1e-5f

typedef unsigned long long ull;
typedef unsigned int u32;

// ---------------- device scratch -------------------------------------------
__device__ __align__(16) float g_A[(size_t)NTYPES * NNODES * DIM];
__device__ __align__(16) float g_B[(size_t)NTYPES * NNODES * DIM];
__device__ __align__(16) float g_acc[(size_t)NTYPES * NNODES * DIM];
__device__ __align__(8)  int2  g_idx[(size_t)NTYPES * NEDGES];   // {src,dst}
__device__ int   g_deg[NTYPES * NNODES];
__device__ float g_sum[NTYPES * DIM];
__device__ float g_sq[NTYPES * DIM];
__device__ float g_s[NTYPES * DIM];
__device__ float g_c[NTYPES * DIM];
__device__ int   g_is64;

__device__ __forceinline__ float elu(float x) {
    return x > 0.f ? x : (__expf(x) - 1.f);
}

__device__ __forceinline__ u32 smem_u32(const void* p) {
    u32 a;
    asm("{ .reg .u64 t; cvta.to.shared.u64 t, %1; cvt.u32.u64 %0, t; }"
        : "=r"(a) : "l"(p));
    return a;
}

// pack two f32 -> bf16x2 (v0 -> low half / first element, v1 -> high half)
#define CVT_BF16X2(r, v0, v1) \
    asm("cvt.rn.satfinite.bf16x2.f32 %0, %1, %2;" : "=r"(r) : "f"(v1), "f"(v0))

#define LDSM_X4(r, a) \
    asm volatile("ldmatrix.sync.aligned.m8n8.x4.shared.b16 {%0,%1,%2,%3}, [%4];" \
                 : "=r"((r)[0]), "=r"((r)[1]), "=r"((r)[2]), "=r"((r)[3]) : "r"(a))
#define LDSM_X4_T(r, a) \
    asm volatile("ldmatrix.sync.aligned.m8n8.x4.trans.shared.b16 {%0,%1,%2,%3}, [%4];" \
                 : "=r"((r)[0]), "=r"((r)[1]), "=r"((r)[2]), "=r"((r)[3]) : "r"(a))
#define MMA16816(c, a, b0, b1) \
    asm volatile("mma.sync.aligned.m16n8k16.row.col.f32.bf16.bf16.f32 " \
                 "{%0,%1,%2,%3}, {%4,%5,%6,%7}, {%8,%9}, {%0,%1,%2,%3};" \
                 : "+f"((c)[0]), "+f"((c)[1]), "+f"((c)[2]), "+f"((c)[3]) \
                 : "r"((a)[0]), "r"((a)[1]), "r"((a)[2]), "r"((a)[3]), \
                   "r"(b0), "r"(b1))

// ---------------- edge-index dtype detection --------------------------------
__global__ void k_detect(const int* __restrict__ e) {
    if (threadIdx.x == 0 && blockIdx.x == 0) {
        int is64 = 1;
        for (int i = 1; i < 256; i += 2)
            if (e[i] != 0) { is64 = 0; break; }
        g_is64 = is64;
    }
}

// ---------------- index conversion -------------------------------------------
__global__ void __launch_bounds__(256) k_convert(const void* __restrict__ esrc_raw,
                                                 const void* __restrict__ edst_raw) {
    const size_t i = (size_t)blockIdx.x * 256 + threadIdx.x;
    if (i >= (size_t)NTYPES * NEDGES) return;
    int s, d;
    if (g_is64) {
        s = (int)((const long long*)esrc_raw)[i];
        d = (int)((const long long*)edst_raw)[i];
    } else {
        s = ((const int*)esrc_raw)[i];
        d = ((const int*)edst_raw)[i];
    }
    g_idx[i] = make_int2(s, d);
}

// ---------------- zero-init --------------------------------------------------
__global__ void k_zero() {
    size_t stride = (size_t)gridDim.x * blockDim.x;
    size_t i = (size_t)blockIdx.x * blockDim.x + threadIdx.x;
    float4 z = make_float4(0.f, 0.f, 0.f, 0.f);
    float4* a4 = reinterpret_cast<float4*>(g_acc);
    size_t n4 = (size_t)NTYPES * NNODES * DIM / 4;
    for (size_t k = i; k < n4; k += stride) a4[k] = z;
    for (size_t k = i; k < (size_t)NTYPES * NNODES; k += stride) g_deg[k] = 0;
    if (i < NTYPES * DIM) { g_sum[i] = 0.f; g_sq[i] = 0.f; }
}

// ---------------- per-node precompute (unchanged from R9) --------------------
__global__ void __launch_bounds__(256) k_pre(const float* __restrict__ F,
                                             const float* __restrict__ W1,
                                             const float* __restrict__ b1) {
    __shared__ float Fs[64 * 68];
    __shared__ float Ws[64 * 64];
    const int tid = threadIdx.x;
    const int t = blockIdx.y;
    const int half = blockIdx.z;

    const float* Wsrc = W1 + ((size_t)t * 128 + (size_t)half * 64) * 64;
    for (int i = tid; i < 1024; i += 256)
        reinterpret_cast<float4*>(Ws)[i] = reinterpret_cast<const float4*>(Wsrc)[i];

    const int nl = tid >> 2, q = tid & 3;
    const int n = blockIdx.x * 64 + nl;
    {
        const int nc = (n < NNODES) ? n : (NNODES - 1);
        const float4* fr = reinterpret_cast<const float4*>(F + (size_t)nc * DIM + q * 16);
        const float mask = (n < NNODES) ? 1.f : 0.f;
#pragma unroll
        for (int i = 0; i < 4; i++) {
            float4 v = fr[i];
            v.x *= mask; v.y *= mask; v.z *= mask; v.w *= mask;
            *reinterpret_cast<float4*>(&Fs[nl * 68 + q * 16 + i * 4]) = v;
        }
    }
    __syncthreads();

    const int ng = (tid >> 4) << 2;
    const int og = (tid & 15) << 2;
    float acc[4][4] = {};
#pragma unroll 16
    for (int k = 0; k < 64; k++) {
        float a[4];
#pragma unroll
        for (int i = 0; i < 4; i++) a[i] = Fs[(ng + i) * 68 + k];
        float4 w = *reinterpret_cast<const float4*>(&Ws[k * 64 + og]);
        const float wa[4] = {w.x, w.y, w.z, w.w};
#pragma unroll
        for (int i = 0; i < 4; i++)
#pragma unroll
            for (int j = 0; j < 4; j++) acc[i][j] += a[i] * wa[j];
    }

    float bb[4] = {0.f, 0.f, 0.f, 0.f};
    if (half == 0) {
        float4 bv = *reinterpret_cast<const float4*>(&b1[t * DIM + og]);
        bb[0] = bv.x; bb[1] = bv.y; bb[2] = bv.z; bb[3] = bv.w;
    }
    float* dst = (half ? g_B : g_A);
#pragma unroll
    for (int i = 0; i < 4; i++) {
        int nn = blockIdx.x * 64 + ng + i;
        if (nn < NNODES) {
            float4 r = make_float4(acc[i][0] + bb[0], acc[i][1] + bb[1],
                                   acc[i][2] + bb[2], acc[i][3] + bb[3]);
            *reinterpret_cast<float4*>(
                &dst[(((size_t)t * NNODES + nn) << 6) + og]) = r;
        }
    }
}

// ---------------- main edge kernel: HMMA (mma.sync) phase B ------------------
// 64 edges per CTA, 256 threads, static smem ~38.4KB.
// hn tiles: [edge][72 halves] (144B stride -> ldmatrix conflict-free)
// W2 tiles: [k][72 halves]     (row-major k x n, loaded via ldmatrix.trans)
__global__ void __launch_bounds__(256) k_edge(const float* __restrict__ lng,
                                              const float* __restrict__ lnb,
                                              const float* __restrict__ W2,
                                              const float* __restrict__ b2) {
    __shared__ u32 hnHI[64 * 36];   // 9216 B (u32 stride 36 = 72 halves)
    __shared__ u32 hnLO[64 * 36];
    __shared__ u32 w2HI[64 * 36];
    __shared__ u32 w2LO[64 * 36];
    __shared__ int dsts[64];
    __shared__ float b2s[64], lngs[64], lnbs[64], ssum[64], ssq[64];

    const int tid = threadIdx.x;
    const int wid = tid >> 5;
    const int lane = tid & 31;
    const int t = blockIdx.y;

    // prologue: W2 -> bf16 hi/lo smem tiles; affine params
    {
        const float* W2p = W2 + (size_t)t * 4096;
        for (int p = tid; p < 2048; p += 256) {
            const int k = p >> 5, c = p & 31;
            const float2 w = *reinterpret_cast<const float2*>(W2p + k * 64 + 2 * c);
            u32 hp; CVT_BF16X2(hp, w.x, w.y);
            const float f0 = __uint_as_float(hp << 16);
            const float f1 = __uint_as_float(hp & 0xFFFF0000u);
            u32 lp; CVT_BF16X2(lp, w.x - f0, w.y - f1);
            w2HI[k * 36 + c] = hp;
            w2LO[k * 36 + c] = lp;
        }
        if (tid < 64) {
            lngs[tid] = lng[t * DIM + tid];
            lnbs[tid] = lnb[t * DIM + tid];
            b2s[tid]  = b2[t * DIM + tid];
            ssum[tid] = 0.f; ssq[tid] = 0.f;
        }
    }
    __syncthreads();

    // ---------- phase A: gather + ELU + LayerNorm -> bf16 hi/lo tiles --------
    const int el = tid >> 2, q = tid & 3;
    const size_t ge = (size_t)blockIdx.x * 64 + el;     // 12500*64 == NEDGES
    const int2 sd = g_idx[(size_t)t * NEDGES + ge];
    const int src = sd.x, dst = sd.y;

    float h[16];
    float sm = 0.f, sq = 0.f;
    {
        const float4* ap = reinterpret_cast<const float4*>(
            g_A + (((size_t)t * NNODES + (size_t)src) << 6) + q * 16);
        const float4* bp = reinterpret_cast<const float4*>(
            g_B + (((size_t)t * NNODES + (size_t)dst) << 6) + q * 16);
        float4 av[4], bv[4];
#pragma unroll
        for (int i = 0; i < 4; i++) av[i] = ap[i];
#pragma unroll
        for (int i = 0; i < 4; i++) bv[i] = bp[i];
#pragma unroll
        for (int i = 0; i < 4; i++) {
            float v0 = elu(av[i].x + bv[i].x), v1 = elu(av[i].y + bv[i].y);
            float v2 = elu(av[i].z + bv[i].z), v3 = elu(av[i].w + bv[i].w);
            h[i * 4 + 0] = v0; h[i * 4 + 1] = v1;
            h[i * 4 + 2] = v2; h[i * 4 + 3] = v3;
            sm += v0 + v1 + v2 + v3;
            sq += v0 * v0 + v1 * v1 + v2 * v2 + v3 * v3;
        }
    }
    sm += __shfl_xor_sync(0xffffffffu, sm, 1);
    sq += __shfl_xor_sync(0xffffffffu, sq, 1);
    sm += __shfl_xor_sync(0xffffffffu, sm, 2);
    sq += __shfl_xor_sync(0xffffffffu, sq, 2);
    const float mu = sm * (1.f / 64.f);
    const float var = sq * (1.f / 64.f) - mu * mu;
    const float rstd = rsqrtf(var + EPSLN);

    {
        u32 hi[8], lo[8];
#pragma unroll
        for (int i = 0; i < 8; i++) {
            const int ch = q * 16 + 2 * i;
            const float v0 = (h[2 * i]     - mu) * rstd * lngs[ch]     + lnbs[ch];
            const float v1 = (h[2 * i + 1] - mu) * rstd * lngs[ch + 1] + lnbs[ch + 1];
            u32 hp; CVT_BF16X2(hp, v0, v1);
            const float f0 = __uint_as_float(hp << 16);
            const float f1 = __uint_as_float(hp & 0xFFFF0000u);
            u32 lp; CVT_BF16X2(lp, v0 - f0, v1 - f1);
            hi[i] = hp; lo[i] = lp;
        }
        u32* dh = &hnHI[el * 36 + q * 8];
        u32* dl = &hnLO[el * 36 + q * 8];
        *reinterpret_cast<uint4*>(dh)     = make_uint4(hi[0], hi[1], hi[2], hi[3]);
        *reinterpret_cast<uint4*>(dh + 4) = make_uint4(hi[4], hi[5], hi[6], hi[7]);
        *reinterpret_cast<uint4*>(dl)     = make_uint4(lo[0], lo[1], lo[2], lo[3]);
        *reinterpret_cast<uint4*>(dl + 4) = make_uint4(lo[4], lo[5], lo[6], lo[7]);
    }
    if (q == 0) dsts[el] = dst;
    __syncthreads();

    // ---------- phase B: P[64x64] = hn @ W2 via mma.sync, bf16 2-term split --
    // warp tile: 16 edges (ew) x 32 ch (nw). D = AhiBhi + AloBhi + AhiBlo.
    const int ew = wid & 3, nw = wid >> 2;
    const int mg = lane >> 3, rr = lane & 7;
    const int arow = ew * 16 + (mg & 1) * 8 + rr;
    const u32 aoff = (u32)(arow * 144 + ((mg >> 1) * 8) * 2);
    const u32 aHbase = smem_u32(hnHI) + aoff;
    const u32 aLbase = smem_u32(hnLO) + aoff;
    const int bkrow = (mg & 1) * 8 + rr;
    const u32 w2Hbase = smem_u32(w2HI);
    const u32 w2Lbase = smem_u32(w2LO);

    float c[4][4];
#pragma unroll
    for (int j = 0; j < 4; j++)
#pragma unroll
        for (int i = 0; i < 4; i++) c[j][i] = 0.f;

#pragma unroll
    for (int kc = 0; kc < 4; kc++) {
        u32 ah[4], al[4];
        LDSM_X4(ah, aHbase + kc * 32);
        LDSM_X4(al, aLbase + kc * 32);
        const u32 brow = (u32)((kc * 16 + bkrow) * 144);
#pragma unroll
        for (int pr = 0; pr < 2; pr++) {
            const u32 nb = (u32)((nw * 32 + pr * 16 + (mg >> 1) * 8) * 2);
            u32 bh[4], bl[4];
            LDSM_X4_T(bh, w2Hbase + brow + nb);
            LDSM_X4_T(bl, w2Lbase + brow + nb);
            MMA16816(c[pr * 2],     ah, bh[0], bh[1]);
            MMA16816(c[pr * 2],     al, bh[0], bh[1]);
            MMA16816(c[pr * 2],     ah, bl[0], bl[1]);
            MMA16816(c[pr * 2 + 1], ah, bh[2], bh[3]);
            MMA16816(c[pr * 2 + 1], al, bh[2], bh[3]);
            MMA16816(c[pr * 2 + 1], ah, bl[2], bl[3]);
        }
    }

    // ---------- phase C: bias + ELU + scatter + BN stats from C frags --------
    const int r0 = lane >> 2, cc = (lane & 3) * 2;
    const int e0 = ew * 16 + r0;
    const int d0 = dsts[e0], d1 = dsts[e0 + 8];
    float cs[8], cq[8];
#pragma unroll
    for (int o = 0; o < 8; o++) { cs[o] = 0.f; cq[o] = 0.f; }

#pragma unroll
    for (int j = 0; j < 4; j++) {
        const int ncol = nw * 32 + j * 8 + cc;
        const float b0 = b2s[ncol], b1 = b2s[ncol + 1];
        const float p00 = elu(c[j][0] + b0);
        const float p01 = elu(c[j][1] + b1);
        const float p10 = elu(c[j][2] + b0);
        const float p11 = elu(c[j][3] + b1);
        float* a0 = g_acc + (((size_t)t * NNODES + d0) << 6) + ncol;
        asm volatile("red.global.add.v2.f32 [%0], {%1,%2};"
                     :: "l"(a0), "f"(p00), "f"(p01) : "memory");
        float* a1 = g_acc + (((size_t)t * NNODES + d1) << 6) + ncol;
        asm volatile("red.global.add.v2.f32 [%0], {%1,%2};"
                     :: "l"(a1), "f"(p10), "f"(p11) : "memory");
        cs[j * 2]     += p00 + p10;
        cs[j * 2 + 1] += p01 + p11;
        cq[j * 2]     += p00 * p00 + p10 * p10;
        cq[j * 2 + 1] += p01 * p01 + p11 * p11;
    }
    // reduce over the 8 row-lanes (same lane&3) per warp
#pragma unroll
    for (int o = 0; o < 8; o++) {
        cs[o] += __shfl_xor_sync(0xffffffffu, cs[o], 4);
        cq[o] += __shfl_xor_sync(0xffffffffu, cq[o], 4);
        cs[o] += __shfl_xor_sync(0xffffffffu, cs[o], 8);
        cq[o] += __shfl_xor_sync(0xffffffffu, cq[o], 8);
        cs[o] += __shfl_xor_sync(0xffffffffu, cs[o], 16);
        cq[o] += __shfl_xor_sync(0xffffffffu, cq[o], 16);
    }
    if (lane < 4) {
#pragma unroll
        for (int j = 0; j < 4; j++) {
            const int ncol = nw * 32 + j * 8 + lane * 2;
            atomicAdd(&ssum[ncol],     cs[j * 2]);
            atomicAdd(&ssum[ncol + 1], cs[j * 2 + 1]);
            atomicAdd(&ssq[ncol],      cq[j * 2]);
            atomicAdd(&ssq[ncol + 1],  cq[j * 2 + 1]);
        }
    }
    if (nw == 0 && lane < 16)
        atomicAdd(&g_deg[t * NNODES + dsts[ew * 16 + lane]], 1);

    __syncthreads();
    if (tid < 64) {
        atomicAdd(&g_sum[t * DIM + tid], ssum[tid]);
        atomicAdd(&g_sq[t * DIM + tid], ssq[tid]);
    }
}

// ---------------- BN stats finalize ------------------------------------------
__global__ void k_stats(const float* __restrict__ bng, const float* __restrict__ bnb) {
    int i = threadIdx.x;
    if (i < NTYPES * DIM) {
        float mean = g_sum[i] * (1.f / NEDGES);
        float var = g_sq[i] * (1.f / NEDGES) - mean * mean;
        float s = bng[i] * rsqrtf(fmaxf(var, 0.f) + EPSLN);
        g_s[i] = s;
        g_c[i] = bnb[i] - mean * s;
    }
}

// ---------------- final (unchanged from R9) ----------------------------------
__global__ void __launch_bounds__(256) k_final(const float* __restrict__ F,
                                               const float* __restrict__ Wr,
                                               const float* __restrict__ br,
                                               float* __restrict__ out) {
    __shared__ float Ws[64 * 64];
    __shared__ float aT[64 * 72];
    const int tid = threadIdx.x;
    for (int i = tid; i < 1024; i += 256)
        reinterpret_cast<float4*>(Ws)[i] = reinterpret_cast<const float4*>(Wr)[i];

    const int nl = tid >> 2, q = tid & 3;
    const int n = blockIdx.x * 64 + nl;
    float v[16];
#pragma unroll
    for (int i = 0; i < 16; i++) v[i] = 0.f;
    if (n < NNODES) {
#pragma unroll
        for (int t = 0; t < NTYPES; t++) {
            const float4* op = reinterpret_cast<const float4*>(
                g_acc + (((size_t)t * NNODES + n) << 6) + q * 16);
            float dg = (float)g_deg[t * NNODES + n];
#pragma unroll
            for (int i = 0; i < 4; i++) {
                float4 o = op[i];
                int ch = q * 16 + i * 4;
                v[i * 4 + 0] += o.x * g_s[t * DIM + ch + 0] + dg * g_c[t * DIM + ch + 0];
                v[i * 4 + 1] += o.y * g_s[t * DIM + ch + 1] + dg * g_c[t * DIM + ch + 1];
                v[i * 4 + 2] += o.z * g_s[t * DIM + ch + 2] + dg * g_c[t * DIM + ch + 2];
                v[i * 4 + 3] += o.w * g_s[t * DIM + ch + 3] + dg * g_c[t * DIM + ch + 3];
            }
        }
    }
#pragma unroll
    for (int i = 0; i < 16; i++) aT[(q * 16 + i) * 72 + nl] = v[i];
    __syncthreads();

    const int ng = (tid >> 4) << 2;
    const int og = (tid & 15) << 2;
    float acc[4][4] = {};
    const float* apx = &aT[ng];
    const float* wpx = &Ws[og];
#pragma unroll 16
    for (int k = 0; k < 64; k++) {
        float4 av = *reinterpret_cast<const float4*>(apx); apx += 72;
        float4 wv = *reinterpret_cast<const float4*>(wpx); wpx += 64;
        const float aa[4] = {av.x, av.y, av.z, av.w};
        const float wa[4] = {wv.x, wv.y, wv.z, wv.w};
#pragma unroll
        for (int i = 0; i < 4; i++)
#pragma unroll
            for (int j = 0; j < 4; j++) acc[i][j] += aa[i] * wa[j];
    }

    float4 brv = *reinterpret_cast<const float4*>(&br[og]);
    const float bra[4] = {brv.x, brv.y, brv.z, brv.w};
#pragma unroll
    for (int i = 0; i < 4; i++) {
        int nn = blockIdx.x * 64 + ng + i;
        if (nn < NNODES) {
            float4 f = *reinterpret_cast<const float4*>(&F[(size_t)nn * DIM + og]);
            float4 r = make_float4(acc[i][0] + bra[0] + f.x,
                                   acc[i][1] + bra[1] + f.y,
                                   acc[i][2] + bra[2] + f.z,
                                   acc[i][3] + bra[3] + f.w);
            *reinterpret_cast<float4*>(&out[(size_t)nn * DIM + og]) = r;
        }
    }
}

// ---------------- launch ------------------------------------------------------
extern "C" void kernel_launch(void* const* d_in, const int* in_sizes, int n_in,
                              void* d_out, int out_size) {
    const float* F   = (const float*)d_in[0];
    const float* W1  = (const float*)d_in[1];
    const float* b1  = (const float*)d_in[2];
    const float* lng = (const float*)d_in[3];
    const float* lnb = (const float*)d_in[4];
    const float* W2  = (const float*)d_in[5];
    const float* b2  = (const float*)d_in[6];
    const float* bng = (const float*)d_in[7];
    const float* bnb = (const float*)d_in[8];
    const float* Wr  = (const float*)d_in[9];
    const float* br  = (const float*)d_in[10];
    const void*  esrc = d_in[11];
    const void*  edst = d_in[12];

    k_detect<<<1, 32>>>((const int*)esrc);
    k_convert<<<(NTYPES * NEDGES + 255) / 256, 256>>>(esrc, edst);
    k_zero<<<2048, 256>>>();

    dim3 gpre((NNODES + 63) / 64, NTYPES, 2);
    k_pre<<<gpre, 256>>>(F, W1, b1);

    dim3 gedge(NEDGES / 64, NTYPES, 1);
    k_edge<<<gedge, 256>>>(lng, lnb, W2, b2);

    k_stats<<<1, 256>>>(bng, bnb);

    k_final<<<(NNODES + 63) / 64, 256>>>(F, Wr, br, (float*)d_out);
}

// round 13
// speedup vs baseline: 1.7692x; 1.1859x over previous
#include <cuda_runtime.h>
#include <cstdint>
#include <cstddef>

#define NNODES 50000
#define NEDGES 800000
#define NTYPES 3
#define DIM    64
#define EPSLN  1e-5f
#define EPC    128              // edges per CTA (800000/128 = 6250)

typedef unsigned long long ull;
typedef unsigned int u32;

// ---------------- device scratch -------------------------------------------
__device__ __align__(16) float g_A[(size_t)NTYPES * NNODES * DIM];
__device__ __align__(16) float g_B[(size_t)NTYPES * NNODES * DIM];
__device__ __align__(16) float g_acc[(size_t)NTYPES * NNODES * DIM];
__device__ __align__(8)  int2  g_idx[(size_t)NTYPES * NEDGES];   // {src,dst}
__device__ __align__(16) u32   g_w2p[NTYPES][2 * 2304];          // hi/lo W2 images, padded k*36+c
__device__ int   g_deg[NTYPES * NNODES];
__device__ float g_sum[NTYPES * DIM];
__device__ float g_sq[NTYPES * DIM];
__device__ float g_s[NTYPES * DIM];
__device__ float g_c[NTYPES * DIM];
__device__ int   g_is64;

__device__ __forceinline__ float elu(float x) {
    return x > 0.f ? x : (__expf(x) - 1.f);
}

__device__ __forceinline__ u32 smem_u32(const void* p) {
    u32 a;
    asm("{ .reg .u64 t; cvta.to.shared.u64 t, %1; cvt.u32.u64 %0, t; }"
        : "=r"(a) : "l"(p));
    return a;
}

// pack two f32 -> bf16x2 (v0 -> low half, v1 -> high half)
#define CVT_BF16X2(r, v0, v1) \
    asm("cvt.rn.satfinite.bf16x2.f32 %0, %1, %2;" : "=r"(r) : "f"(v1), "f"(v0))

#define LDSM_X4(r, a) \
    asm volatile("ldmatrix.sync.aligned.m8n8.x4.shared.b16 {%0,%1,%2,%3}, [%4];" \
                 : "=r"((r)[0]), "=r"((r)[1]), "=r"((r)[2]), "=r"((r)[3]) : "r"(a))
#define LDSM_X4_T(r, a) \
    asm volatile("ldmatrix.sync.aligned.m8n8.x4.trans.shared.b16 {%0,%1,%2,%3}, [%4];" \
                 : "=r"((r)[0]), "=r"((r)[1]), "=r"((r)[2]), "=r"((r)[3]) : "r"(a))
#define MMA16816(c, a, b0, b1) \
    asm volatile("mma.sync.aligned.m16n8k16.row.col.f32.bf16.bf16.f32 " \
                 "{%0,%1,%2,%3}, {%4,%5,%6,%7}, {%8,%9}, {%0,%1,%2,%3};" \
                 : "+f"((c)[0]), "+f"((c)[1]), "+f"((c)[2]), "+f"((c)[3]) \
                 : "r"((a)[0]), "r"((a)[1]), "r"((a)[2]), "r"((a)[3]), \
                   "r"(b0), "r"(b1))

// ---------------- edge-index dtype detection --------------------------------
__global__ void k_detect(const int* __restrict__ e) {
    if (threadIdx.x == 0 && blockIdx.x == 0) {
        int is64 = 1;
        for (int i = 1; i < 256; i += 2)
            if (e[i] != 0) { is64 = 0; break; }
        g_is64 = is64;
    }
}

// ---------------- index conversion -------------------------------------------
__global__ void __launch_bounds__(256) k_convert(const void* __restrict__ esrc_raw,
                                                 const void* __restrict__ edst_raw) {
    const size_t i = (size_t)blockIdx.x * 256 + threadIdx.x;
    if (i >= (size_t)NTYPES * NEDGES) return;
    int s, d;
    if (g_is64) {
        s = (int)((const long long*)esrc_raw)[i];
        d = (int)((const long long*)edst_raw)[i];
    } else {
        s = ((const int*)esrc_raw)[i];
        d = ((const int*)edst_raw)[i];
    }
    g_idx[i] = make_int2(s, d);
}

// ---------------- W2 -> bf16 hi/lo padded gmem image -------------------------
// layout matches the smem tile: [k 0..63][c 0..31] at k*36+c (u32 = 2 halves)
__global__ void __launch_bounds__(256) k_w2(const float* __restrict__ W2) {
    const int t = blockIdx.x;
    const float* W2p = W2 + (size_t)t * 4096;
    for (int p = threadIdx.x; p < 2048; p += 256) {
        const int k = p >> 5, c = p & 31;
        const float2 w = *reinterpret_cast<const float2*>(W2p + k * 64 + 2 * c);
        u32 hp; CVT_BF16X2(hp, w.x, w.y);
        const float f0 = __uint_as_float(hp << 16);
        const float f1 = __uint_as_float(hp & 0xFFFF0000u);
        u32 lp; CVT_BF16X2(lp, w.x - f0, w.y - f1);
        g_w2p[t][k * 36 + c] = hp;
        g_w2p[t][2304 + k * 36 + c] = lp;
    }
}

// ---------------- zero-init --------------------------------------------------
__global__ void k_zero() {
    size_t stride = (size_t)gridDim.x * blockDim.x;
    size_t i = (size_t)blockIdx.x * blockDim.x + threadIdx.x;
    float4 z = make_float4(0.f, 0.f, 0.f, 0.f);
    float4* a4 = reinterpret_cast<float4*>(g_acc);
    size_t n4 = (size_t)NTYPES * NNODES * DIM / 4;
    for (size_t k = i; k < n4; k += stride) a4[k] = z;
    for (size_t k = i; k < (size_t)NTYPES * NNODES; k += stride) g_deg[k] = 0;
    if (i < NTYPES * DIM) { g_sum[i] = 0.f; g_sq[i] = 0.f; }
}

// ---------------- per-node precompute (unchanged) ----------------------------
__global__ void __launch_bounds__(256) k_pre(const float* __restrict__ F,
                                             const float* __restrict__ W1,
                                             const float* __restrict__ b1) {
    __shared__ float Fs[64 * 68];
    __shared__ float Ws[64 * 64];
    const int tid = threadIdx.x;
    const int t = blockIdx.y;
    const int half = blockIdx.z;

    const float* Wsrc = W1 + ((size_t)t * 128 + (size_t)half * 64) * 64;
    for (int i = tid; i < 1024; i += 256)
        reinterpret_cast<float4*>(Ws)[i] = reinterpret_cast<const float4*>(Wsrc)[i];

    const int nl = tid >> 2, q = tid & 3;
    const int n = blockIdx.x * 64 + nl;
    {
        const int nc = (n < NNODES) ? n : (NNODES - 1);
        const float4* fr = reinterpret_cast<const float4*>(F + (size_t)nc * DIM + q * 16);
        const float mask = (n < NNODES) ? 1.f : 0.f;
#pragma unroll
        for (int i = 0; i < 4; i++) {
            float4 v = fr[i];
            v.x *= mask; v.y *= mask; v.z *= mask; v.w *= mask;
            *reinterpret_cast<float4*>(&Fs[nl * 68 + q * 16 + i * 4]) = v;
        }
    }
    __syncthreads();

    const int ng = (tid >> 4) << 2;
    const int og = (tid & 15) << 2;
    float acc[4][4] = {};
#pragma unroll 16
    for (int k = 0; k < 64; k++) {
        float a[4];
#pragma unroll
        for (int i = 0; i < 4; i++) a[i] = Fs[(ng + i) * 68 + k];
        float4 w = *reinterpret_cast<const float4*>(&Ws[k * 64 + og]);
        const float wa[4] = {w.x, w.y, w.z, w.w};
#pragma unroll
        for (int i = 0; i < 4; i++)
#pragma unroll
            for (int j = 0; j < 4; j++) acc[i][j] += a[i] * wa[j];
    }

    float bb[4] = {0.f, 0.f, 0.f, 0.f};
    if (half == 0) {
        float4 bv = *reinterpret_cast<const float4*>(&b1[t * DIM + og]);
        bb[0] = bv.x; bb[1] = bv.y; bb[2] = bv.z; bb[3] = bv.w;
    }
    float* dst = (half ? g_B : g_A);
#pragma unroll
    for (int i = 0; i < 4; i++) {
        int nn = blockIdx.x * 64 + ng + i;
        if (nn < NNODES) {
            float4 r = make_float4(acc[i][0] + bb[0], acc[i][1] + bb[1],
                                   acc[i][2] + bb[2], acc[i][3] + bb[3]);
            *reinterpret_cast<float4*>(
                &dst[(((size_t)t * NNODES + nn) << 6) + og]) = r;
        }
    }
}

// ---------------- main edge kernel: 128 edges, HMMA, B-frag reuse ------------
// Dynamic smem layout (bytes):
//   hnHI  u32[128][36]   0       18432
//   hnLO  u32[128][36]   18432   18432
//   w2HI  u32[64][36]    36864   9216
//   w2LO  u32[64][36]    46080   9216
//   dsts  int[128]       55296   512
//   b2s/lngs/lnbs/ssum/ssq f[64] 55808.. (5*256)
extern __shared__ char smem_raw[];
#define OFF_HNHI 0
#define OFF_HNLO 18432
#define OFF_W2HI 36864
#define OFF_W2LO 46080
#define OFF_DSTS 55296
#define OFF_B2S  55808
#define OFF_LNG  56064
#define OFF_LNB  56320
#define OFF_SSUM 56576
#define OFF_SSQ  56832
#define SMEM_BYTES 57088

__global__ void __launch_bounds__(256) k_edge(const float* __restrict__ lng,
                                              const float* __restrict__ lnb,
                                              const float* __restrict__ b2) {
    const int tid = threadIdx.x;
    const int wid = tid >> 5;
    const int lane = tid & 31;
    const int t = blockIdx.y;

    u32* hnHI = (u32*)(smem_raw + OFF_HNHI);
    u32* hnLO = (u32*)(smem_raw + OFF_HNLO);
    int* dsts = (int*)(smem_raw + OFF_DSTS);
    float* b2s = (float*)(smem_raw + OFF_B2S);
    float* lngs = (float*)(smem_raw + OFF_LNG);
    float* lnbs = (float*)(smem_raw + OFF_LNB);
    float* ssum = (float*)(smem_raw + OFF_SSUM);
    float* ssq  = (float*)(smem_raw + OFF_SSQ);

    // prologue: copy precomputed W2 hi/lo images (18KB, coalesced); params
    {
        const uint4* src = reinterpret_cast<const uint4*>(g_w2p[t]);
        uint4* dst = reinterpret_cast<uint4*>(smem_raw + OFF_W2HI);
        for (int i = tid; i < 1152; i += 256) dst[i] = src[i];
        if (tid < 64) {
            lngs[tid] = lng[t * DIM + tid];
            lnbs[tid] = lnb[t * DIM + tid];
            b2s[tid]  = b2[t * DIM + tid];
            ssum[tid] = 0.f; ssq[tid] = 0.f;
        }
    }
    __syncthreads();

    // ---------- phase A: gather + ELU + LayerNorm, 2 batches of 64 edges -----
    const int el = tid >> 2, q = tid & 3;
    int2 eidx[2];
    {
        const size_t off0 = (size_t)t * NEDGES + (size_t)blockIdx.x * EPC + el;
        eidx[0] = g_idx[off0];
        eidx[1] = g_idx[off0 + 64];
    }
#pragma unroll
    for (int b = 0; b < 2; b++) {
        const int e_loc = b * 64 + el;
        const int src = eidx[b].x, dst = eidx[b].y;
        float h[16];
        float sm = 0.f, sq = 0.f;
        {
            const float4* ap = reinterpret_cast<const float4*>(
                g_A + (((size_t)t * NNODES + (size_t)src) << 6) + q * 16);
            const float4* bp = reinterpret_cast<const float4*>(
                g_B + (((size_t)t * NNODES + (size_t)dst) << 6) + q * 16);
            float4 av[4], bv[4];
#pragma unroll
            for (int i = 0; i < 4; i++) av[i] = ap[i];
#pragma unroll
            for (int i = 0; i < 4; i++) bv[i] = bp[i];
#pragma unroll
            for (int i = 0; i < 4; i++) {
                float v0 = elu(av[i].x + bv[i].x), v1 = elu(av[i].y + bv[i].y);
                float v2 = elu(av[i].z + bv[i].z), v3 = elu(av[i].w + bv[i].w);
                h[i * 4 + 0] = v0; h[i * 4 + 1] = v1;
                h[i * 4 + 2] = v2; h[i * 4 + 3] = v3;
                sm += v0 + v1 + v2 + v3;
                sq += v0 * v0 + v1 * v1 + v2 * v2 + v3 * v3;
            }
        }
        sm += __shfl_xor_sync(0xffffffffu, sm, 1);
        sq += __shfl_xor_sync(0xffffffffu, sq, 1);
        sm += __shfl_xor_sync(0xffffffffu, sm, 2);
        sq += __shfl_xor_sync(0xffffffffu, sq, 2);
        const float mu = sm * (1.f / 64.f);
        const float var = sq * (1.f / 64.f) - mu * mu;
        const float rstd = rsqrtf(var + EPSLN);

        u32 hi[8], lo[8];
#pragma unroll
        for (int i = 0; i < 8; i++) {
            const int ch = q * 16 + 2 * i;
            const float v0 = (h[2 * i]     - mu) * rstd * lngs[ch]     + lnbs[ch];
            const float v1 = (h[2 * i + 1] - mu) * rstd * lngs[ch + 1] + lnbs[ch + 1];
            u32 hp; CVT_BF16X2(hp, v0, v1);
            const float f0 = __uint_as_float(hp << 16);
            const float f1 = __uint_as_float(hp & 0xFFFF0000u);
            u32 lp; CVT_BF16X2(lp, v0 - f0, v1 - f1);
            hi[i] = hp; lo[i] = lp;
        }
        u32* dh = &hnHI[e_loc * 36 + q * 8];
        u32* dl = &hnLO[e_loc * 36 + q * 8];
        *reinterpret_cast<uint4*>(dh)     = make_uint4(hi[0], hi[1], hi[2], hi[3]);
        *reinterpret_cast<uint4*>(dh + 4) = make_uint4(hi[4], hi[5], hi[6], hi[7]);
        *reinterpret_cast<uint4*>(dl)     = make_uint4(lo[0], lo[1], lo[2], lo[3]);
        *reinterpret_cast<uint4*>(dl + 4) = make_uint4(lo[4], lo[5], lo[6], lo[7]);
        if (q == 0) dsts[e_loc] = dst;
    }
    __syncthreads();

    // ---------- phase B: two 16x32 C-tiles per warp, B frags reused ----------
    const int ew = wid & 3, nw = wid >> 2;
    const int mg = lane >> 3, rr = lane & 7;
    const int arow0 = ew * 16 + (mg & 1) * 8 + rr;           // tile 0 rows
    const u32 aoff0 = (u32)(arow0 * 144 + ((mg >> 1) * 8) * 2);
    const u32 aoff1 = aoff0 + (u32)(64 * 144);               // tile 1 rows (+64 edges)
    const u32 aHb = smem_u32(smem_raw + OFF_HNHI);
    const u32 aLb = smem_u32(smem_raw + OFF_HNLO);
    const int bkrow = (mg & 1) * 8 + rr;
    const u32 bHb = smem_u32(smem_raw + OFF_W2HI);
    const u32 bLb = smem_u32(smem_raw + OFF_W2LO);

    float c0[4][4], c1[4][4];
#pragma unroll
    for (int j = 0; j < 4; j++)
#pragma unroll
        for (int i = 0; i < 4; i++) { c0[j][i] = 0.f; c1[j][i] = 0.f; }

#pragma unroll
    for (int kc = 0; kc < 4; kc++) {
        u32 ah0[4], al0[4], ah1[4], al1[4];
        LDSM_X4(ah0, aHb + aoff0 + kc * 32);
        LDSM_X4(al0, aLb + aoff0 + kc * 32);
        LDSM_X4(ah1, aHb + aoff1 + kc * 32);
        LDSM_X4(al1, aLb + aoff1 + kc * 32);
        const u32 brow = (u32)((kc * 16 + bkrow) * 144);
#pragma unroll
        for (int pr = 0; pr < 2; pr++) {
            const u32 nb = (u32)((nw * 32 + pr * 16 + (mg >> 1) * 8) * 2);
            u32 bh[4], bl[4];
            LDSM_X4_T(bh, bHb + brow + nb);
            LDSM_X4_T(bl, bLb + brow + nb);
            MMA16816(c0[pr * 2],     ah0, bh[0], bh[1]);
            MMA16816(c0[pr * 2],     al0, bh[0], bh[1]);
            MMA16816(c0[pr * 2],     ah0, bl[0], bl[1]);
            MMA16816(c0[pr * 2 + 1], ah0, bh[2], bh[3]);
            MMA16816(c0[pr * 2 + 1], al0, bh[2], bh[3]);
            MMA16816(c0[pr * 2 + 1], ah0, bl[2], bl[3]);
            MMA16816(c1[pr * 2],     ah1, bh[0], bh[1]);
            MMA16816(c1[pr * 2],     al1, bh[0], bh[1]);
            MMA16816(c1[pr * 2],     ah1, bl[0], bl[1]);
            MMA16816(c1[pr * 2 + 1], ah1, bh[2], bh[3]);
            MMA16816(c1[pr * 2 + 1], al1, bh[2], bh[3]);
            MMA16816(c1[pr * 2 + 1], ah1, bl[2], bl[3]);
        }
    }

    // degrees: one atomic per thread for the 128 edges
    if (tid < 128) atomicAdd(&g_deg[t * NNODES + dsts[tid]], 1);

    // ---------- phase C: bias + ELU + scatter + BN stats ---------------------
    const int r0 = lane >> 2, cc = (lane & 3) * 2;
    float cs[8], cq[8];
#pragma unroll
    for (int o = 0; o < 8; o++) { cs[o] = 0.f; cq[o] = 0.f; }

#pragma unroll
    for (int tile = 0; tile < 2; tile++) {
        float (*cf)[4] = tile ? c1 : c0;
        const int e0 = tile * 64 + ew * 16 + r0;
        const int d0 = dsts[e0], d1 = dsts[e0 + 8];
#pragma unroll
        for (int j = 0; j < 4; j++) {
            const int ncol = nw * 32 + j * 8 + cc;
            const float b0 = b2s[ncol], b1 = b2s[ncol + 1];
            const float p00 = elu(cf[j][0] + b0);
            const float p01 = elu(cf[j][1] + b1);
            const float p10 = elu(cf[j][2] + b0);
            const float p11 = elu(cf[j][3] + b1);
            float* a0 = g_acc + (((size_t)t * NNODES + d0) << 6) + ncol;
            asm volatile("red.global.add.v2.f32 [%0], {%1,%2};"
                         :: "l"(a0), "f"(p00), "f"(p01) : "memory");
            float* a1 = g_acc + (((size_t)t * NNODES + d1) << 6) + ncol;
            asm volatile("red.global.add.v2.f32 [%0], {%1,%2};"
                         :: "l"(a1), "f"(p10), "f"(p11) : "memory");
            cs[j * 2]     += p00 + p10;
            cs[j * 2 + 1] += p01 + p11;
            cq[j * 2]     += p00 * p00 + p10 * p10;
            cq[j * 2 + 1] += p01 * p01 + p11 * p11;
        }
    }
#pragma unroll
    for (int o = 0; o < 8; o++) {
        cs[o] += __shfl_xor_sync(0xffffffffu, cs[o], 4);
        cq[o] += __shfl_xor_sync(0xffffffffu, cq[o], 4);
        cs[o] += __shfl_xor_sync(0xffffffffu, cs[o], 8);
        cq[o] += __shfl_xor_sync(0xffffffffu, cq[o], 8);
        cs[o] += __shfl_xor_sync(0xffffffffu, cs[o], 16);
        cq[o] += __shfl_xor_sync(0xffffffffu, cq[o], 16);
    }
    if (lane < 4) {
#pragma unroll
        for (int j = 0; j < 4; j++) {
            const int ncol = nw * 32 + j * 8 + lane * 2;
            atomicAdd(&ssum[ncol],     cs[j * 2]);
            atomicAdd(&ssum[ncol + 1], cs[j * 2 + 1]);
            atomicAdd(&ssq[ncol],      cq[j * 2]);
            atomicAdd(&ssq[ncol + 1],  cq[j * 2 + 1]);
        }
    }
    __syncthreads();
    if (tid < 64) {
        atomicAdd(&g_sum[t * DIM + tid], ssum[tid]);
        atomicAdd(&g_sq[t * DIM + tid], ssq[tid]);
    }
}

// ---------------- BN stats finalize ------------------------------------------
__global__ void k_stats(const float* __restrict__ bng, const float* __restrict__ bnb) {
    int i = threadIdx.x;
    if (i < NTYPES * DIM) {
        float mean = g_sum[i] * (1.f / NEDGES);
        float var = g_sq[i] * (1.f / NEDGES) - mean * mean;
        float s = bng[i] * rsqrtf(fmaxf(var, 0.f) + EPSLN);
        g_s[i] = s;
        g_c[i] = bnb[i] - mean * s;
    }
}

// ---------------- final (unchanged) ------------------------------------------
__global__ void __launch_bounds__(256) k_final(const float* __restrict__ F,
                                               const float* __restrict__ Wr,
                                               const float* __restrict__ br,
                                               float* __restrict__ out) {
    __shared__ float Ws[64 * 64];
    __shared__ float aT[64 * 72];
    const int tid = threadIdx.x;
    for (int i = tid; i < 1024; i += 256)
        reinterpret_cast<float4*>(Ws)[i] = reinterpret_cast<const float4*>(Wr)[i];

    const int nl = tid >> 2, q = tid & 3;
    const int n = blockIdx.x * 64 + nl;
    float v[16];
#pragma unroll
    for (int i = 0; i < 16; i++) v[i] = 0.f;
    if (n < NNODES) {
#pragma unroll
        for (int t = 0; t < NTYPES; t++) {
            const float4* op = reinterpret_cast<const float4*>(
                g_acc + (((size_t)t * NNODES + n) << 6) + q * 16);
            float dg = (float)g_deg[t * NNODES + n];
#pragma unroll
            for (int i = 0; i < 4; i++) {
                float4 o = op[i];
                int ch = q * 16 + i * 4;
                v[i * 4 + 0] += o.x * g_s[t * DIM + ch + 0] + dg * g_c[t * DIM + ch + 0];
                v[i * 4 + 1] += o.y * g_s[t * DIM + ch + 1] + dg * g_c[t * DIM + ch + 1];
                v[i * 4 + 2] += o.z * g_s[t * DIM + ch + 2] + dg * g_c[t * DIM + ch + 2];
                v[i * 4 + 3] += o.w * g_s[t * DIM + ch + 3] + dg * g_c[t * DIM + ch + 3];
            }
        }
    }
#pragma unroll
    for (int i = 0; i < 16; i++) aT[(q * 16 + i) * 72 + nl] = v[i];
    __syncthreads();

    const int ng = (tid >> 4) << 2;
    const int og = (tid & 15) << 2;
    float acc[4][4] = {};
    const float* apx = &aT[ng];
    const float* wpx = &Ws[og];
#pragma unroll 16
    for (int k = 0; k < 64; k++) {
        float4 av = *reinterpret_cast<const float4*>(apx); apx += 72;
        float4 wv = *reinterpret_cast<const float4*>(wpx); wpx += 64;
        const float aa[4] = {av.x, av.y, av.z, av.w};
        const float wa[4] = {wv.x, wv.y, wv.z, wv.w};
#pragma unroll
        for (int i = 0; i < 4; i++)
#pragma unroll
            for (int j = 0; j < 4; j++) acc[i][j] += aa[i] * wa[j];
    }

    float4 brv = *reinterpret_cast<const float4*>(&br[og]);
    const float bra[4] = {brv.x, brv.y, brv.z, brv.w};
#pragma unroll
    for (int i = 0; i < 4; i++) {
        int nn = blockIdx.x * 64 + ng + i;
        if (nn < NNODES) {
            float4 f = *reinterpret_cast<const float4*>(&F[(size_t)nn * DIM + og]);
            float4 r = make_float4(acc[i][0] + bra[0] + f.x,
                                   acc[i][1] + bra[1] + f.y,
                                   acc[i][2] + bra[2] + f.z,
                                   acc[i][3] + bra[3] + f.w);
            *reinterpret_cast<float4*>(&out[(size_t)nn * DIM + og]) = r;
        }
    }
}

// ---------------- launch ------------------------------------------------------
extern "C" void kernel_launch(void* const* d_in, const int* in_sizes, int n_in,
                              void* d_out, int out_size) {
    const float* F   = (const float*)d_in[0];
    const float* W1  = (const float*)d_in[1];
    const float* b1  = (const float*)d_in[2];
    const float* lng = (const float*)d_in[3];
    const float* lnb = (const float*)d_in[4];
    const float* W2  = (const float*)d_in[5];
    const float* b2  = (const float*)d_in[6];
    const float* bng = (const float*)d_in[7];
    const float* bnb = (const float*)d_in[8];
    const float* Wr  = (const float*)d_in[9];
    const float* br  = (const float*)d_in[10];
    const void*  esrc = d_in[11];
    const void*  edst = d_in[12];

    cudaFuncSetAttribute(k_edge, cudaFuncAttributeMaxDynamicSharedMemorySize,
                         SMEM_BYTES);

    k_detect<<<1, 32>>>((const int*)esrc);
    k_convert<<<(NTYPES * NEDGES + 255) / 256, 256>>>(esrc, edst);
    k_w2<<<NTYPES, 256>>>(W2);
    k_zero<<<2048, 256>>>();

    dim3 gpre((NNODES + 63) / 64, NTYPES, 2);
    k_pre<<<gpre, 256>>>(F, W1, b1);

    dim3 gedge(NEDGES / EPC, NTYPES, 1);
    k_edge<<<gedge, 256, SMEM_BYTES>>>(lng, lnb, b2);

    k_stats<<<1, 256>>>(bng, bnb);

    k_final<<<(NNODES + 63) / 64, 256>>>(F, Wr, br, (float*)d_out);
}

// round 14
// speedup vs baseline: 1.7695x; 1.0002x over previous
#include <cuda_runtime.h>
#include <cstdint>
#include <cstddef>

#define NNODES 50000
#define NEDGES 800000
#define NTYPES 3
#define DIM    64
#define EPSLN  1e-5f
#define EPC    128              // edges per CTA (800000/128 = 6250)

typedef unsigned long long ull;
typedef unsigned int u32;

// ---------------- device scratch -------------------------------------------
__device__ __align__(16) float g_A[(size_t)NTYPES * NNODES * DIM];
__device__ __align__(16) float g_B[(size_t)NTYPES * NNODES * DIM];
__device__ __align__(16) float g_acc[(size_t)NTYPES * NNODES * DIM];
__device__ __align__(8)  int2  g_idx[(size_t)NTYPES * NEDGES];   // {src,dst}
__device__ __align__(16) u32   g_w2p[NTYPES][2 * 2304];          // hi/lo W2 images, padded k*36+c
__device__ int   g_deg[NTYPES * NNODES];
__device__ float g_sum[NTYPES * DIM];
__device__ float g_sq[NTYPES * DIM];
__device__ float g_s[NTYPES * DIM];
__device__ float g_c[NTYPES * DIM];
__device__ int   g_is64;

__device__ __forceinline__ float elu(float x) {
    return x > 0.f ? x : (__expf(x) - 1.f);
}

__device__ __forceinline__ u32 smem_u32(const void* p) {
    u32 a;
    asm("{ .reg .u64 t; cvta.to.shared.u64 t, %1; cvt.u32.u64 %0, t; }"
        : "=r"(a) : "l"(p));
    return a;
}

// pack two f32 -> bf16x2 (v0 -> low half, v1 -> high half)
#define CVT_BF16X2(r, v0, v1) \
    asm("cvt.rn.satfinite.bf16x2.f32 %0, %1, %2;" : "=r"(r) : "f"(v1), "f"(v0))

#define LDSM_X4(r, a) \
    asm volatile("ldmatrix.sync.aligned.m8n8.x4.shared.b16 {%0,%1,%2,%3}, [%4];" \
                 : "=r"((r)[0]), "=r"((r)[1]), "=r"((r)[2]), "=r"((r)[3]) : "r"(a))
#define LDSM_X4_T(r, a) \
    asm volatile("ldmatrix.sync.aligned.m8n8.x4.trans.shared.b16 {%0,%1,%2,%3}, [%4];" \
                 : "=r"((r)[0]), "=r"((r)[1]), "=r"((r)[2]), "=r"((r)[3]) : "r"(a))
#define MMA16816(c, a, b0, b1) \
    asm volatile("mma.sync.aligned.m16n8k16.row.col.f32.bf16.bf16.f32 " \
                 "{%0,%1,%2,%3}, {%4,%5,%6,%7}, {%8,%9}, {%0,%1,%2,%3};" \
                 : "+f"((c)[0]), "+f"((c)[1]), "+f"((c)[2]), "+f"((c)[3]) \
                 : "r"((a)[0]), "r"((a)[1]), "r"((a)[2]), "r"((a)[3]), \
                   "r"(b0), "r"(b1))

// ---------------- edge-index dtype detection --------------------------------
__global__ void k_detect(const int* __restrict__ e) {
    if (threadIdx.x == 0 && blockIdx.x == 0) {
        int is64 = 1;
        for (int i = 1; i < 256; i += 2)
            if (e[i] != 0) { is64 = 0; break; }
        g_is64 = is64;
    }
}

// ---------------- index conversion -------------------------------------------
__global__ void __launch_bounds__(256) k_convert(const void* __restrict__ esrc_raw,
                                                 const void* __restrict__ edst_raw) {
    const size_t i = (size_t)blockIdx.x * 256 + threadIdx.x;
    if (i >= (size_t)NTYPES * NEDGES) return;
    int s, d;
    if (g_is64) {
        s = (int)((const long long*)esrc_raw)[i];
        d = (int)((const long long*)edst_raw)[i];
    } else {
        s = ((const int*)esrc_raw)[i];
        d = ((const int*)edst_raw)[i];
    }
    g_idx[i] = make_int2(s, d);
}

// ---------------- W2 -> bf16 hi/lo padded gmem image -------------------------
// layout matches the smem tile: [k 0..63][c 0..31] at k*36+c (u32 = 2 halves)
__global__ void __launch_bounds__(256) k_w2(const float* __restrict__ W2) {
    const int t = blockIdx.x;
    const float* W2p = W2 + (size_t)t * 4096;
    for (int p = threadIdx.x; p < 2048; p += 256) {
        const int k = p >> 5, c = p & 31;
        const float2 w = *reinterpret_cast<const float2*>(W2p + k * 64 + 2 * c);
        u32 hp; CVT_BF16X2(hp, w.x, w.y);
        const float f0 = __uint_as_float(hp << 16);
        const float f1 = __uint_as_float(hp & 0xFFFF0000u);
        u32 lp; CVT_BF16X2(lp, w.x - f0, w.y - f1);
        g_w2p[t][k * 36 + c] = hp;
        g_w2p[t][2304 + k * 36 + c] = lp;
    }
}

// ---------------- zero-init --------------------------------------------------
__global__ void k_zero() {
    size_t stride = (size_t)gridDim.x * blockDim.x;
    size_t i = (size_t)blockIdx.x * blockDim.x + threadIdx.x;
    float4 z = make_float4(0.f, 0.f, 0.f, 0.f);
    float4* a4 = reinterpret_cast<float4*>(g_acc);
    size_t n4 = (size_t)NTYPES * NNODES * DIM / 4;
    for (size_t k = i; k < n4; k += stride) a4[k] = z;
    for (size_t k = i; k < (size_t)NTYPES * NNODES; k += stride) g_deg[k] = 0;
    if (i < NTYPES * DIM) { g_sum[i] = 0.f; g_sq[i] = 0.f; }
}

// ---------------- per-node precompute (unchanged) ----------------------------
__global__ void __launch_bounds__(256) k_pre(const float* __restrict__ F,
                                             const float* __restrict__ W1,
                                             const float* __restrict__ b1) {
    __shared__ float Fs[64 * 68];
    __shared__ float Ws[64 * 64];
    const int tid = threadIdx.x;
    const int t = blockIdx.y;
    const int half = blockIdx.z;

    const float* Wsrc = W1 + ((size_t)t * 128 + (size_t)half * 64) * 64;
    for (int i = tid; i < 1024; i += 256)
        reinterpret_cast<float4*>(Ws)[i] = reinterpret_cast<const float4*>(Wsrc)[i];

    const int nl = tid >> 2, q = tid & 3;
    const int n = blockIdx.x * 64 + nl;
    {
        const int nc = (n < NNODES) ? n : (NNODES - 1);
        const float4* fr = reinterpret_cast<const float4*>(F + (size_t)nc * DIM + q * 16);
        const float mask = (n < NNODES) ? 1.f : 0.f;
#pragma unroll
        for (int i = 0; i < 4; i++) {
            float4 v = fr[i];
            v.x *= mask; v.y *= mask; v.z *= mask; v.w *= mask;
            *reinterpret_cast<float4*>(&Fs[nl * 68 + q * 16 + i * 4]) = v;
        }
    }
    __syncthreads();

    const int ng = (tid >> 4) << 2;
    const int og = (tid & 15) << 2;
    float acc[4][4] = {};
#pragma unroll 16
    for (int k = 0; k < 64; k++) {
        float a[4];
#pragma unroll
        for (int i = 0; i < 4; i++) a[i] = Fs[(ng + i) * 68 + k];
        float4 w = *reinterpret_cast<const float4*>(&Ws[k * 64 + og]);
        const float wa[4] = {w.x, w.y, w.z, w.w};
#pragma unroll
        for (int i = 0; i < 4; i++)
#pragma unroll
            for (int j = 0; j < 4; j++) acc[i][j] += a[i] * wa[j];
    }

    float bb[4] = {0.f, 0.f, 0.f, 0.f};
    if (half == 0) {
        float4 bv = *reinterpret_cast<const float4*>(&b1[t * DIM + og]);
        bb[0] = bv.x; bb[1] = bv.y; bb[2] = bv.z; bb[3] = bv.w;
    }
    float* dst = (half ? g_B : g_A);
#pragma unroll
    for (int i = 0; i < 4; i++) {
        int nn = blockIdx.x * 64 + ng + i;
        if (nn < NNODES) {
            float4 r = make_float4(acc[i][0] + bb[0], acc[i][1] + bb[1],
                                   acc[i][2] + bb[2], acc[i][3] + bb[3]);
            *reinterpret_cast<float4*>(
                &dst[(((size_t)t * NNODES + nn) << 6) + og]) = r;
        }
    }
}

// ---------------- main edge kernel: 128 edges, HMMA, B-frag reuse ------------
// Dynamic smem layout (bytes):
//   hnHI  u32[128][36]   0       18432
//   hnLO  u32[128][36]   18432   18432
//   w2HI  u32[64][36]    36864   9216
//   w2LO  u32[64][36]    46080   9216
//   dsts  int[128]       55296   512
//   b2s/lngs/lnbs/ssum/ssq f[64] 55808.. (5*256)
extern __shared__ char smem_raw[];
#define OFF_HNHI 0
#define OFF_HNLO 18432
#define OFF_W2HI 36864
#define OFF_W2LO 46080
#define OFF_DSTS 55296
#define OFF_B2S  55808
#define OFF_LNG  56064
#define OFF_LNB  56320
#define OFF_SSUM 56576
#define OFF_SSQ  56832
#define SMEM_BYTES 57088

__global__ void __launch_bounds__(256) k_edge(const float* __restrict__ lng,
                                              const float* __restrict__ lnb,
                                              const float* __restrict__ b2) {
    const int tid = threadIdx.x;
    const int wid = tid >> 5;
    const int lane = tid & 31;
    const int t = blockIdx.y;

    u32* hnHI = (u32*)(smem_raw + OFF_HNHI);
    u32* hnLO = (u32*)(smem_raw + OFF_HNLO);
    int* dsts = (int*)(smem_raw + OFF_DSTS);
    float* b2s = (float*)(smem_raw + OFF_B2S);
    float* lngs = (float*)(smem_raw + OFF_LNG);
    float* lnbs = (float*)(smem_raw + OFF_LNB);
    float* ssum = (float*)(smem_raw + OFF_SSUM);
    float* ssq  = (float*)(smem_raw + OFF_SSQ);

    // prologue: copy precomputed W2 hi/lo images (18KB, coalesced); params
    {
        const uint4* src = reinterpret_cast<const uint4*>(g_w2p[t]);
        uint4* dst = reinterpret_cast<uint4*>(smem_raw + OFF_W2HI);
        for (int i = tid; i < 1152; i += 256) dst[i] = src[i];
        if (tid < 64) {
            lngs[tid] = lng[t * DIM + tid];
            lnbs[tid] = lnb[t * DIM + tid];
            b2s[tid]  = b2[t * DIM + tid];
            ssum[tid] = 0.f; ssq[tid] = 0.f;
        }
    }
    __syncthreads();

    // ---------- phase A: gather + ELU + LayerNorm, 2 batches of 64 edges -----
    const int el = tid >> 2, q = tid & 3;
    int2 eidx[2];
    {
        const size_t off0 = (size_t)t * NEDGES + (size_t)blockIdx.x * EPC + el;
        eidx[0] = g_idx[off0];
        eidx[1] = g_idx[off0 + 64];
    }
#pragma unroll
    for (int b = 0; b < 2; b++) {
        const int e_loc = b * 64 + el;
        const int src = eidx[b].x, dst = eidx[b].y;
        float h[16];
        float sm = 0.f, sq = 0.f;
        {
            const float4* ap = reinterpret_cast<const float4*>(
                g_A + (((size_t)t * NNODES + (size_t)src) << 6) + q * 16);
            const float4* bp = reinterpret_cast<const float4*>(
                g_B + (((size_t)t * NNODES + (size_t)dst) << 6) + q * 16);
            float4 av[4], bv[4];
#pragma unroll
            for (int i = 0; i < 4; i++) av[i] = ap[i];
#pragma unroll
            for (int i = 0; i < 4; i++) bv[i] = bp[i];
#pragma unroll
            for (int i = 0; i < 4; i++) {
                float v0 = elu(av[i].x + bv[i].x), v1 = elu(av[i].y + bv[i].y);
                float v2 = elu(av[i].z + bv[i].z), v3 = elu(av[i].w + bv[i].w);
                h[i * 4 + 0] = v0; h[i * 4 + 1] = v1;
                h[i * 4 + 2] = v2; h[i * 4 + 3] = v3;
                sm += v0 + v1 + v2 + v3;
                sq += v0 * v0 + v1 * v1 + v2 * v2 + v3 * v3;
            }
        }
        sm += __shfl_xor_sync(0xffffffffu, sm, 1);
        sq += __shfl_xor_sync(0xffffffffu, sq, 1);
        sm += __shfl_xor_sync(0xffffffffu, sm, 2);
        sq += __shfl_xor_sync(0xffffffffu, sq, 2);
        const float mu = sm * (1.f / 64.f);
        const float var = sq * (1.f / 64.f) - mu * mu;
        const float rstd = rsqrtf(var + EPSLN);

        u32 hi[8], lo[8];
#pragma unroll
        for (int i = 0; i < 8; i++) {
            const int ch = q * 16 + 2 * i;
            const float v0 = (h[2 * i]     - mu) * rstd * lngs[ch]     + lnbs[ch];
            const float v1 = (h[2 * i + 1] - mu) * rstd * lngs[ch + 1] + lnbs[ch + 1];
            u32 hp; CVT_BF16X2(hp, v0, v1);
            const float f0 = __uint_as_float(hp << 16);
            const float f1 = __uint_as_float(hp & 0xFFFF0000u);
            u32 lp; CVT_BF16X2(lp, v0 - f0, v1 - f1);
            hi[i] = hp; lo[i] = lp;
        }
        u32* dh = &hnHI[e_loc * 36 + q * 8];
        u32* dl = &hnLO[e_loc * 36 + q * 8];
        *reinterpret_cast<uint4*>(dh)     = make_uint4(hi[0], hi[1], hi[2], hi[3]);
        *reinterpret_cast<uint4*>(dh + 4) = make_uint4(hi[4], hi[5], hi[6], hi[7]);
        *reinterpret_cast<uint4*>(dl)     = make_uint4(lo[0], lo[1], lo[2], lo[3]);
        *reinterpret_cast<uint4*>(dl + 4) = make_uint4(lo[4], lo[5], lo[6], lo[7]);
        if (q == 0) dsts[e_loc] = dst;
    }
    __syncthreads();

    // ---------- phase B: two 16x32 C-tiles per warp, B frags reused ----------
    const int ew = wid & 3, nw = wid >> 2;
    const int mg = lane >> 3, rr = lane & 7;
    const int arow0 = ew * 16 + (mg & 1) * 8 + rr;           // tile 0 rows
    const u32 aoff0 = (u32)(arow0 * 144 + ((mg >> 1) * 8) * 2);
    const u32 aoff1 = aoff0 + (u32)(64 * 144);               // tile 1 rows (+64 edges)
    const u32 aHb = smem_u32(smem_raw + OFF_HNHI);
    const u32 aLb = smem_u32(smem_raw + OFF_HNLO);
    const int bkrow = (mg & 1) * 8 + rr;
    const u32 bHb = smem_u32(smem_raw + OFF_W2HI);
    const u32 bLb = smem_u32(smem_raw + OFF_W2LO);

    float c0[4][4], c1[4][4];
#pragma unroll
    for (int j = 0; j < 4; j++)
#pragma unroll
        for (int i = 0; i < 4; i++) { c0[j][i] = 0.f; c1[j][i] = 0.f; }

#pragma unroll
    for (int kc = 0; kc < 4; kc++) {
        u32 ah0[4], al0[4], ah1[4], al1[4];
        LDSM_X4(ah0, aHb + aoff0 + kc * 32);
        LDSM_X4(al0, aLb + aoff0 + kc * 32);
        LDSM_X4(ah1, aHb + aoff1 + kc * 32);
        LDSM_X4(al1, aLb + aoff1 + kc * 32);
        const u32 brow = (u32)((kc * 16 + bkrow) * 144);
#pragma unroll
        for (int pr = 0; pr < 2; pr++) {
            const u32 nb = (u32)((nw * 32 + pr * 16 + (mg >> 1) * 8) * 2);
            u32 bh[4], bl[4];
            LDSM_X4_T(bh, bHb + brow + nb);
            LDSM_X4_T(bl, bLb + brow + nb);
            MMA16816(c0[pr * 2],     ah0, bh[0], bh[1]);
            MMA16816(c0[pr * 2],     al0, bh[0], bh[1]);
            MMA16816(c0[pr * 2],     ah0, bl[0], bl[1]);
            MMA16816(c0[pr * 2 + 1], ah0, bh[2], bh[3]);
            MMA16816(c0[pr * 2 + 1], al0, bh[2], bh[3]);
            MMA16816(c0[pr * 2 + 1], ah0, bl[2], bl[3]);
            MMA16816(c1[pr * 2],     ah1, bh[0], bh[1]);
            MMA16816(c1[pr * 2],     al1, bh[0], bh[1]);
            MMA16816(c1[pr * 2],     ah1, bl[0], bl[1]);
            MMA16816(c1[pr * 2 + 1], ah1, bh[2], bh[3]);
            MMA16816(c1[pr * 2 + 1], al1, bh[2], bh[3]);
            MMA16816(c1[pr * 2 + 1], ah1, bl[2], bl[3]);
        }
    }

    // degrees: one atomic per thread for the 128 edges
    if (tid < 128) atomicAdd(&g_deg[t * NNODES + dsts[tid]], 1);

    // ---------- phase C: bias + ELU + scatter + BN stats ---------------------
    const int r0 = lane >> 2, cc = (lane & 3) * 2;
    float cs[8], cq[8];
#pragma unroll
    for (int o = 0; o < 8; o++) { cs[o] = 0.f; cq[o] = 0.f; }

#pragma unroll
    for (int tile = 0; tile < 2; tile++) {
        float (*cf)[4] = tile ? c1 : c0;
        const int e0 = tile * 64 + ew * 16 + r0;
        const int d0 = dsts[e0], d1 = dsts[e0 + 8];
#pragma unroll
        for (int j = 0; j < 4; j++) {
            const int ncol = nw * 32 + j * 8 + cc;
            const float b0 = b2s[ncol], b1 = b2s[ncol + 1];
            const float p00 = elu(cf[j][0] + b0);
            const float p01 = elu(cf[j][1] + b1);
            const float p10 = elu(cf[j][2] + b0);
            const float p11 = elu(cf[j][3] + b1);
            float* a0 = g_acc + (((size_t)t * NNODES + d0) << 6) + ncol;
            asm volatile("red.global.add.v2.f32 [%0], {%1,%2};"
                         :: "l"(a0), "f"(p00), "f"(p01) : "memory");
            float* a1 = g_acc + (((size_t)t * NNODES + d1) << 6) + ncol;
            asm volatile("red.global.add.v2.f32 [%0], {%1,%2};"
                         :: "l"(a1), "f"(p10), "f"(p11) : "memory");
            cs[j * 2]     += p00 + p10;
            cs[j * 2 + 1] += p01 + p11;
            cq[j * 2]     += p00 * p00 + p10 * p10;
            cq[j * 2 + 1] += p01 * p01 + p11 * p11;
        }
    }
#pragma unroll
    for (int o = 0; o < 8; o++) {
        cs[o] += __shfl_xor_sync(0xffffffffu, cs[o], 4);
        cq[o] += __shfl_xor_sync(0xffffffffu, cq[o], 4);
        cs[o] += __shfl_xor_sync(0xffffffffu, cs[o], 8);
        cq[o] += __shfl_xor_sync(0xffffffffu, cq[o], 8);
        cs[o] += __shfl_xor_sync(0xffffffffu, cs[o], 16);
        cq[o] += __shfl_xor_sync(0xffffffffu, cq[o], 16);
    }
    if (lane < 4) {
#pragma unroll
        for (int j = 0; j < 4; j++) {
            const int ncol = nw * 32 + j * 8 + lane * 2;
            atomicAdd(&ssum[ncol],     cs[j * 2]);
            atomicAdd(&ssum[ncol + 1], cs[j * 2 + 1]);
            atomicAdd(&ssq[ncol],      cq[j * 2]);
            atomicAdd(&ssq[ncol + 1],  cq[j * 2 + 1]);
        }
    }
    __syncthreads();
    if (tid < 64) {
        atomicAdd(&g_sum[t * DIM + tid], ssum[tid]);
        atomicAdd(&g_sq[t * DIM + tid], ssq[tid]);
    }
}

// ---------------- BN stats finalize ------------------------------------------
__global__ void k_stats(const float* __restrict__ bng, const float* __restrict__ bnb) {
    int i = threadIdx.x;
    if (i < NTYPES * DIM) {
        float mean = g_sum[i] * (1.f / NEDGES);
        float var = g_sq[i] * (1.f / NEDGES) - mean * mean;
        float s = bng[i] * rsqrtf(fmaxf(var, 0.f) + EPSLN);
        g_s[i] = s;
        g_c[i] = bnb[i] - mean * s;
    }
}

// ---------------- final (unchanged) ------------------------------------------
__global__ void __launch_bounds__(256) k_final(const float* __restrict__ F,
                                               const float* __restrict__ Wr,
                                               const float* __restrict__ br,
                                               float* __restrict__ out) {
    __shared__ float Ws[64 * 64];
    __shared__ float aT[64 * 72];
    const int tid = threadIdx.x;
    for (int i = tid; i < 1024; i += 256)
        reinterpret_cast<float4*>(Ws)[i] = reinterpret_cast<const float4*>(Wr)[i];

    const int nl = tid >> 2, q = tid & 3;
    const int n = blockIdx.x * 64 + nl;
    float v[16];
#pragma unroll
    for (int i = 0; i < 16; i++) v[i] = 0.f;
    if (n < NNODES) {
#pragma unroll
        for (int t = 0; t < NTYPES; t++) {
            const float4* op = reinterpret_cast<const float4*>(
                g_acc + (((size_t)t * NNODES + n) << 6) + q * 16);
            float dg = (float)g_deg[t * NNODES + n];
#pragma unroll
            for (int i = 0; i < 4; i++) {
                float4 o = op[i];
                int ch = q * 16 + i * 4;
                v[i * 4 + 0] += o.x * g_s[t * DIM + ch + 0] + dg * g_c[t * DIM + ch + 0];
                v[i * 4 + 1] += o.y * g_s[t * DIM + ch + 1] + dg * g_c[t * DIM + ch + 1];
                v[i * 4 + 2] += o.z * g_s[t * DIM + ch + 2] + dg * g_c[t * DIM + ch + 2];
                v[i * 4 + 3] += o.w * g_s[t * DIM + ch + 3] + dg * g_c[t * DIM + ch + 3];
            }
        }
    }
#pragma unroll
    for (int i = 0; i < 16; i++) aT[(q * 16 + i) * 72 + nl] = v[i];
    __syncthreads();

    const int ng = (tid >> 4) << 2;
    const int og = (tid & 15) << 2;
    float acc[4][4] = {};
    const float* apx = &aT[ng];
    const float* wpx = &Ws[og];
#pragma unroll 16
    for (int k = 0; k < 64; k++) {
        float4 av = *reinterpret_cast<const float4*>(apx); apx += 72;
        float4 wv = *reinterpret_cast<const float4*>(wpx); wpx += 64;
        const float aa[4] = {av.x, av.y, av.z, av.w};
        const float wa[4] = {wv.x, wv.y, wv.z, wv.w};
#pragma unroll
        for (int i = 0; i < 4; i++)
#pragma unroll
            for (int j = 0; j < 4; j++) acc[i][j] += aa[i] * wa[j];
    }

    float4 brv = *reinterpret_cast<const float4*>(&br[og]);
    const float bra[4] = {brv.x, brv.y, brv.z, brv.w};
#pragma unroll
    for (int i = 0; i < 4; i++) {
        int nn = blockIdx.x * 64 + ng + i;
        if (nn < NNODES) {
            float4 f = *reinterpret_cast<const float4*>(&F[(size_t)nn * DIM + og]);
            float4 r = make_float4(acc[i][0] + bra[0] + f.x,
                                   acc[i][1] + bra[1] + f.y,
                                   acc[i][2] + bra[2] + f.z,
                                   acc[i][3] + bra[3] + f.w);
            *reinterpret_cast<float4*>(&out[(size_t)nn * DIM + og]) = r;
        }
    }
}

// ---------------- launch ------------------------------------------------------
extern "C" void kernel_launch(void* const* d_in, const int* in_sizes, int n_in,
                              void* d_out, int out_size) {
    const float* F   = (const float*)d_in[0];
    const float* W1  = (const float*)d_in[1];
    const float* b1  = (const float*)d_in[2];
    const float* lng = (const float*)d_in[3];
    const float* lnb = (const float*)d_in[4];
    const float* W2  = (const float*)d_in[5];
    const float* b2  = (const float*)d_in[6];
    const float* bng = (const float*)d_in[7];
    const float* bnb = (const float*)d_in[8];
    const float* Wr  = (const float*)d_in[9];
    const float* br  = (const float*)d_in[10];
    const void*  esrc = d_in[11];
    const void*  edst = d_in[12];

    cudaFuncSetAttribute(k_edge, cudaFuncAttributeMaxDynamicSharedMemorySize,
                         SMEM_BYTES);

    k_detect<<<1, 32>>>((const int*)esrc);
    k_convert<<<(NTYPES * NEDGES + 255) / 256, 256>>>(esrc, edst);
    k_w2<<<NTYPES, 256>>>(W2);
    k_zero<<<2048, 256>>>();

    dim3 gpre((NNODES + 63) / 64, NTYPES, 2);
    k_pre<<<gpre, 256>>>(F, W1, b1);

    dim3 gedge(NEDGES / EPC, NTYPES, 1);
    k_edge<<<gedge, 256, SMEM_BYTES>>>(lng, lnb, b2);

    k_stats<<<1, 256>>>(bng, bnb);

    k_final<<<(NNODES + 63) / 64, 256>>>(F, Wr, br, (float*)d_out);
}